// round 14
// baseline (speedup 1.0000x reference)
#include <cuda_runtime.h>
#include <cuda_fp16.h>
#include <cstdint>

#define N 8192
#define D 128
#define NUM_CLASSES 256
#define MARGIN 0.3f
#define MAXH 96

#define BM 128
#define BN 128
#define BKP 40                        // padded row: 80B = 20 banks, ldmatrix conflict-free
#define CHUNK_ELEMS (128 * BKP)       // 5120 fp16 per (rowblock, kchunk)
#define CHUNK_BYTES (CHUNK_ELEMS * 2) // 10240 B
#define STAGE_BYTES (2 * CHUNK_BYTES) // A + B chunk = 20480 B
#define SMEM_DATA   (4 * STAGE_BYTES) // all 4 k-chunks resident = 81920 B
#define SMEM_TOTAL  (SMEM_DATA + 32)  // + 4 mbarriers

// Persistent device state (module globals; no allocation).
__device__ float    g_sq[N];
__device__ int      g_cls[N];
__device__ unsigned g_pos_max[N];     // float bits (written exclusively per class)
__device__ unsigned g_neg_min[N];     // float bits; dsq > 0 so uint order == float order
__device__ int      g_hist[NUM_CLASSES];
__device__ int      g_cnt[NUM_CLASSES];
__device__ int      g_mem[NUM_CLASSES * MAXH];
__device__ float    g_Tc[NUM_CLASSES * D];   // per-class vector sums
__device__ float    g_Sc[NUM_CLASSES];       // per-class sq-norm sums
__device__ float    g_Tall[D];
__device__ float    g_Sall[1];
// tile-major, pre-padded: [block 0..63][kchunk 0..3][row 0..127 * BKP + col]
__device__ __align__(16) __half g_xh[N * 4 * BKP];

__device__ __forceinline__ unsigned su32(const void* p) {
    return (unsigned)__cvta_generic_to_shared(p);
}

#define LDMX4(r0, r1, r2, r3, addr)                                         \
    asm volatile("ldmatrix.sync.aligned.m8n8.x4.shared.b16 {%0,%1,%2,%3}, [%4];" \
                 : "=r"(r0), "=r"(r1), "=r"(r2), "=r"(r3) : "r"(addr))

#define MMA_F16(c0, c1, c2, c3, a, b)                                       \
    asm volatile("mma.sync.aligned.m16n8k16.row.col.f32.f16.f16.f32 "       \
                 "{%0,%1,%2,%3}, {%4,%5,%6,%7}, {%8,%9}, {%0,%1,%2,%3};"    \
                 : "+f"(c0), "+f"(c1), "+f"(c2), "+f"(c3)                    \
                 : "r"((a)[0]), "r"((a)[1]), "r"((a)[2]), "r"((a)[3]),       \
                   "r"((b)[0]), "r"((b)[1]))

__device__ __forceinline__ void mbar_wait(unsigned mbar, unsigned parity) {
    asm volatile("{\n\t.reg .pred P;\n\t"
                 "WL%=:\n\t"
                 "mbarrier.try_wait.parity.acquire.cta.shared::cta.b64 P, [%0], %1, 0x989680;\n\t"
                 "@P bra WD%=;\n\t"
                 "bra WL%=;\n\t"
                 "WD%=:\n\t}"
                 :: "r"(mbar), "r"(parity) : "memory");
}

// ---------------------------------------------------------------------------
// Kernel 0: zero class accumulators + out.
// ---------------------------------------------------------------------------
__global__ void zero_kernel(float* __restrict__ out)
{
    int i = blockIdx.x * blockDim.x + threadIdx.x;
    if (i < NUM_CLASSES * D) g_Tc[i] = 0.f;
    if (i < NUM_CLASSES) { g_Sc[i] = 0.f; g_hist[i] = 0; g_cnt[i] = 0; }
    if (i == 0) { out[0] = 0.f; g_Sall[0] = 0.f; }
}

// ---------------------------------------------------------------------------
// Kernel 1: warp-per-row. Squared norms (fp32) + fp16 cast of X in padded
// tile-major layout (bulk-copy ready).
// ---------------------------------------------------------------------------
__global__ void prep_kernel(const float* __restrict__ x)
{
    int gt   = blockIdx.x * blockDim.x + threadIdx.x;
    int row  = gt >> 5;
    int lane = gt & 31;
    if (row >= N) return;

    float4 v = ((const float4*)(x + (size_t)row * D))[lane];
    float s = v.x * v.x + v.y * v.y + v.z * v.z + v.w * v.w;
    #pragma unroll
    for (int o = 16; o; o >>= 1) s += __shfl_xor_sync(0xffffffffu, s, o);
    if (lane == 0) g_sq[row] = s;

    float f[4] = {v.x, v.y, v.z, v.w};
    unsigned short h[4];
    #pragma unroll
    for (int k = 0; k < 4; k++)
        h[k] = __half_as_ushort(__float2half_rn(f[k]));
    uint2 uh;
    uh.x = (unsigned)h[0] | ((unsigned)h[1] << 16);
    uh.y = (unsigned)h[2] | ((unsigned)h[3] << 16);

    int blk = row >> 7, r = row & 127;
    size_t off = (size_t)(blk * 4 + (lane >> 3)) * CHUNK_ELEMS + r * BKP + (lane & 7) * 4;
    *(uint2*)(g_xh + off) = uh;
}

// ---------------------------------------------------------------------------
// Kernel 2: warp-per-row. Targets (dtype auto-detect), member lists, resets,
// per-class vector/scalar sums via atomics.
// ---------------------------------------------------------------------------
__global__ void init2_kernel(const void* __restrict__ tgt, int tgt_elems,
                             const float* __restrict__ x)
{
    __shared__ int s_is64;
    if (threadIdx.x == 0) {
        const long long* t64 = (const long long*)tgt;
        int is64 = 1;
        int probe = tgt_elems < 8 ? tgt_elems : 8;
        for (int i = 0; i < probe; i++) {
            long long v = t64[i];
            if (v < 0 || v >= NUM_CLASSES) { is64 = 0; break; }
        }
        s_is64 = is64;
    }
    __syncthreads();

    int r    = blockIdx.x * 8 + (threadIdx.x >> 5);
    int lane = threadIdx.x & 31;

    int c = 0;
    if (lane == 0) {
        if (s_is64) c = (int)((const long long*)tgt)[r];
        else        c = ((const int*)tgt)[r];
    }
    c = __shfl_sync(0xffffffffu, c, 0);

    if (lane == 0) {
        g_cls[r]     = c;
        g_neg_min[r] = 0x7F800000u;
        atomicAdd(&g_hist[c], 1);
        int slot = atomicAdd(&g_cnt[c], 1);
        if (slot < MAXH) g_mem[c * MAXH + slot] = r;
        atomicAdd(&g_Sc[c], g_sq[r]);
    }
    float4 v = ((const float4*)(x + (size_t)r * D))[lane];
    float* tc = g_Tc + c * D + lane * 4;
    atomicAdd(tc + 0, v.x);
    atomicAdd(tc + 1, v.y);
    atomicAdd(tc + 2, v.z);
    atomicAdd(tc + 3, v.w);
}

// ---------------------------------------------------------------------------
// Kernel 3: reduce per-class sums -> global sums.
// ---------------------------------------------------------------------------
__global__ void reduce_kernel()
{
    int d = threadIdx.x;   // 0..127
    float s = 0.f;
    for (int c = 0; c < NUM_CLASSES; c++) s += g_Tc[c * D + d];
    g_Tall[d] = s;
    if (d == 0) {
        float ss = 0.f;
        for (int c = 0; c < NUM_CLASSES; c++) ss += g_Sc[c];
        g_Sall[0] = ss;
    }
}

// ---------------------------------------------------------------------------
// Kernel 4: per-class pos_max (exact fp32 same-class pairwise distances).
// ---------------------------------------------------------------------------
__global__ void classmax_kernel(const float* __restrict__ x)
{
    const int c = blockIdx.x;
    int h = g_hist[c];
    if (h > MAXH) h = MAXH;
    __shared__ unsigned smax[MAXH];
    __shared__ int      mem[MAXH];
    const int tid = threadIdx.x;   // 128

    if (tid < MAXH) {
        smax[tid] = 0u;
        mem[tid]  = (tid < h) ? g_mem[c * MAXH + tid] : 0;
    }
    __syncthreads();

    for (int p = tid; p < h * h; p += 128) {
        int a = p / h, b = p % h;
        if (a == b) continue;
        const float4* xa = (const float4*)(x + (size_t)mem[a] * D);
        const float4* xb = (const float4*)(x + (size_t)mem[b] * D);
        float dot = 0.f;
        #pragma unroll
        for (int k = 0; k < 32; k++) {
            float4 va = xa[k], vb = xb[k];
            dot += va.x * vb.x + va.y * vb.y + va.z * vb.z + va.w * vb.w;
        }
        float d2 = fmaxf(g_sq[mem[a]] + g_sq[mem[b]] - 2.f * dot, 1e-12f);
        atomicMax(&smax[a], __float_as_uint(d2));
    }
    __syncthreads();
    if (tid < h) g_pos_max[mem[tid]] = smax[tid];
}

// ---------------------------------------------------------------------------
// Kernel 5: triangular tiled X*X^T, fp16 mma.sync, full-K prefetch via
// cp.async.bulk. Epilogue: masked neg-min only (row + symmetric column pass).
// ---------------------------------------------------------------------------
__global__ __launch_bounds__(256, 2) void dist_kernel()
{
    // decode 1D triangular index -> (bx >= by)
    int t = blockIdx.x;
    int row = (int)((sqrtf(8.f * (float)t + 1.f) - 1.f) * 0.5f);
    while ((row + 1) * (row + 2) / 2 <= t) row++;
    while (row * (row + 1) / 2 > t) row--;
    const int bx = row;
    const int by = t - row * (row + 1) / 2;
    const bool offdiag = (bx != by);
    const int i0 = by * BM, j0 = bx * BN;

    extern __shared__ char smem[];
    const unsigned sbase = su32(smem);

    __shared__ unsigned r_nmin[BM], c_nmin[BN];
    __shared__ float    s_sqi[BM], s_sqj[BN];
    __shared__ int      s_clsi[BM], s_clsj[BN];

    const int tid = threadIdx.x;
    const int wid = tid >> 5, lane = tid & 31;
    const int warp_m = (wid >> 2) * 64;   // 0 or 64
    const int warp_n = (wid & 3) * 32;    // 0,32,64,96

    if (tid < BM) {
        r_nmin[tid] = 0x7F800000u;
        c_nmin[tid] = 0x7F800000u;
        s_sqi[tid]  = g_sq[i0 + tid];
        s_clsi[tid] = g_cls[i0 + tid];
    } else {
        int c = tid - BM;
        s_sqj[c]  = g_sq[j0 + c];
        s_clsj[c] = g_cls[j0 + c];
    }
    if (tid == 0) {
        #pragma unroll
        for (int kb = 0; kb < 4; kb++)
            asm volatile("mbarrier.init.shared.b64 [%0], %1;"
                         :: "r"(sbase + SMEM_DATA + kb * 8), "r"(1u) : "memory");
    }
    __syncthreads();

    if (tid == 0) {
        #pragma unroll
        for (int kb = 0; kb < 4; kb++) {
            unsigned mbar = sbase + SMEM_DATA + kb * 8;
            asm volatile("mbarrier.arrive.expect_tx.shared.b64 _, [%0], %1;"
                         :: "r"(mbar), "r"((unsigned)STAGE_BYTES) : "memory");
            const __half* srcA = g_xh + (size_t)(by * 4 + kb) * CHUNK_ELEMS;
            const __half* srcB = g_xh + (size_t)(bx * 4 + kb) * CHUNK_ELEMS;
            unsigned dstA = sbase + (unsigned)kb * STAGE_BYTES;
            asm volatile("cp.async.bulk.shared::cluster.global.mbarrier::complete_tx::bytes "
                         "[%0], [%1], %2, [%3];"
                         :: "r"(dstA), "l"(srcA), "r"((unsigned)CHUNK_BYTES), "r"(mbar)
                         : "memory");
            asm volatile("cp.async.bulk.shared::cluster.global.mbarrier::complete_tx::bytes "
                         "[%0], [%1], %2, [%3];"
                         :: "r"(dstA + CHUNK_BYTES), "l"(srcB), "r"((unsigned)CHUNK_BYTES), "r"(mbar)
                         : "memory");
        }
    }

    float C[8][8];
    #pragma unroll
    for (int a = 0; a < 8; a++)
        #pragma unroll
        for (int b = 0; b < 8; b++) C[a][b] = 0.f;

    const unsigned aoff = (unsigned)(lane & 15) * (BKP * 2) + (unsigned)(lane >> 4) * 16
                        + (unsigned)warp_m * (BKP * 2);
    const unsigned boff = (unsigned)(((lane >> 4) & 1) * 8 + (lane & 7)) * (BKP * 2)
                        + (unsigned)((lane >> 3) & 1) * 16
                        + (unsigned)warp_n * (BKP * 2);

    #pragma unroll
    for (int kb = 0; kb < 4; kb++) {
        mbar_wait(sbase + SMEM_DATA + kb * 8, 0u);

        const unsigned sb = sbase + (unsigned)kb * STAGE_BYTES;
        const unsigned aA = sb + aoff;
        const unsigned aB = sb + CHUNK_BYTES + boff;

        #pragma unroll
        for (int ks = 0; ks < 2; ks++) {
            const unsigned kbyte = (unsigned)ks * 32;
            unsigned A[4][4], B[4][2];
            #pragma unroll
            for (int mt = 0; mt < 4; mt++) {
                const unsigned moff = (unsigned)(mt * 16) * (BKP * 2) + kbyte;
                LDMX4(A[mt][0], A[mt][1], A[mt][2], A[mt][3], aA + moff);
            }
            #pragma unroll
            for (int bq = 0; bq < 2; bq++) {
                const unsigned noff = (unsigned)(bq * 16) * (BKP * 2) + kbyte;
                unsigned r0, r1, r2, r3;
                LDMX4(r0, r1, r2, r3, aB + noff);
                B[2 * bq][0] = r0; B[2 * bq][1] = r1;
                B[2 * bq + 1][0] = r2; B[2 * bq + 1][1] = r3;
            }
            #pragma unroll
            for (int mt = 0; mt < 4; mt++)
                #pragma unroll
                for (int nt = 0; nt < 4; nt++)
                    MMA_F16(C[2*mt][2*nt], C[2*mt][2*nt+1], C[2*mt+1][2*nt], C[2*mt+1][2*nt+1],
                            A[mt], B[nt]);
        }
    }

    // ---- epilogue: masked neg-min only ----
    const int rg = lane >> 2, cg = lane & 3;
    int kis[8];

    #pragma unroll
    for (int mi = 0; mi < 8; mi++) {
        const int lr   = warp_m + (mi >> 1) * 16 + (mi & 1) * 8 + rg;
        const float si = s_sqi[lr];
        const int   ki = s_clsi[lr];
        kis[mi] = ki;
        float nmin = __uint_as_float(0x7F800000u);
        #pragma unroll
        for (int ci = 0; ci < 8; ci++) {
            const int lc = warp_n + (ci >> 1) * 8 + 2 * cg + (ci & 1);
            float dsq = fmaxf(si + s_sqj[lc] - 2.f * C[mi][ci], 1e-12f);
            C[mi][ci] = dsq;
            if (ki != s_clsj[lc]) nmin = fminf(nmin, dsq);
        }
        #pragma unroll
        for (int o = 1; o <= 2; o <<= 1)
            nmin = fminf(nmin, __shfl_xor_sync(0xffffffffu, nmin, o));
        if (cg == 0) atomicMin(&r_nmin[lr], __float_as_uint(nmin));
    }

    if (offdiag) {
        #pragma unroll
        for (int ci = 0; ci < 8; ci++) {
            const int lc = warp_n + (ci >> 1) * 8 + 2 * cg + (ci & 1);
            const int kj = s_clsj[lc];
            float nmin = __uint_as_float(0x7F800000u);
            #pragma unroll
            for (int mi = 0; mi < 8; mi++)
                if (kis[mi] != kj) nmin = fminf(nmin, C[mi][ci]);
            #pragma unroll
            for (int o = 4; o <= 16; o <<= 1)
                nmin = fminf(nmin, __shfl_xor_sync(0xffffffffu, nmin, o));
            if (lane < 4) atomicMin(&c_nmin[lc], __float_as_uint(nmin));
        }
    }

    __syncthreads();
    if (tid < BM) {
        atomicMin(&g_neg_min[i0 + tid], r_nmin[tid]);
        if (offdiag) atomicMin(&g_neg_min[j0 + tid], c_nmin[tid]);
    }
}

// ---------------------------------------------------------------------------
// Kernel 6: warp-per-row analytic sums + loss terms + mean.
// ---------------------------------------------------------------------------
__global__ void finalize_kernel(const float* __restrict__ x, float* __restrict__ out)
{
    __shared__ float red[8];
    const int tid  = threadIdx.x;
    const int r    = blockIdx.x * 8 + (tid >> 5);
    const int lane = tid & 31;
    const int wq   = tid >> 5;

    const int cls = g_cls[r];
    float4 v  = ((const float4*)(x + (size_t)r * D))[lane];
    float4 tc = ((const float4*)(g_Tc + cls * D))[lane];
    float4 ta = ((const float4*)g_Tall)[lane];
    float dc = v.x * tc.x + v.y * tc.y + v.z * tc.z + v.w * tc.w;
    float da = v.x * ta.x + v.y * ta.y + v.z * ta.z + v.w * ta.w;
    #pragma unroll
    for (int o = 16; o; o >>= 1) {
        dc += __shfl_xor_sync(0xffffffffu, dc, o);
        da += __shfl_xor_sync(0xffffffffu, da, o);
    }

    float lterm = 0.f;
    if (lane == 0) {
        float sq = g_sq[r];
        int   h  = g_hist[cls];
        float psum = (float)h * sq + g_Sc[cls] - 2.f * dc;
        float tot  = (float)N * sq + g_Sall[0] - 2.f * da;
        float nsum = tot - psum;
        float cnt_p = (float)(h - 1);
        float cnt_n = (float)(N - h);
        float sigma_p = psum / cnt_p;
        float sigma_n = nsum / cnt_n;
        float ap = __uint_as_float(g_pos_max[r]) / sigma_p + 0.5f * logf(sigma_p);
        float an = __uint_as_float(g_neg_min[r]) / sigma_n + 0.5f * logf(sigma_n);
        lterm = fmaxf(ap - an + MARGIN, 0.f);
        red[wq] = lterm;
    }
    __syncthreads();
    if (tid == 0) {
        float s = 0.f;
        #pragma unroll
        for (int w = 0; w < 8; w++) s += red[w];
        atomicAdd(out, s * (1.f / (float)N));
    }
}

// ---------------------------------------------------------------------------
extern "C" void kernel_launch(void* const* d_in, const int* in_sizes, int n_in,
                              void* d_out, int out_size)
{
    const float* x = (const float*)d_in[0];
    const void*  t = d_in[1];
    int tgt_elems = (n_in > 1) ? in_sizes[1] : N;

    cudaFuncSetAttribute(dist_kernel, cudaFuncAttributeMaxDynamicSharedMemorySize,
                         SMEM_TOTAL);

    zero_kernel<<<128, 256>>>((float*)d_out);
    prep_kernel<<<N / 8, 256>>>(x);
    init2_kernel<<<N / 8, 256>>>(t, tgt_elems, x);
    reduce_kernel<<<1, 128>>>();
    classmax_kernel<<<NUM_CLASSES, 128>>>(x);
    dist_kernel<<<2080, 256, SMEM_TOTAL>>>();
    finalize_kernel<<<N / 8, 256>>>(x, (float*)d_out);
}